// round 15
// baseline (speedup 1.0000x reference)
#include <cuda_runtime.h>
#include <cuda_fp16.h>
#include <cstdint>

#define N_NODES 50000
#define N_EDGES 800000
#define D_IN    256
#define D_OUT   64
#define NEG_SLOPE 0.2f

// Scratch: support = x @ W^T + b  stored as fp16  [N_NODES, D_OUT]
__device__ __half g_support[N_NODES * D_OUT];
// CSR row pointers for sorted edge_dst
__device__ int g_rowptr[N_NODES + 1];

// ---------------------------------------------------------------------------
// fp16 m16n8k16 mma
// ---------------------------------------------------------------------------
__device__ __forceinline__ void mma_f16(float c[4], const uint32_t a[4], uint32_t b0, uint32_t b1) {
    asm volatile(
        "mma.sync.aligned.m16n8k16.row.col.f32.f16.f16.f32 "
        "{%0,%1,%2,%3}, {%4,%5,%6,%7}, {%8,%9}, {%0,%1,%2,%3};"
        : "+f"(c[0]), "+f"(c[1]), "+f"(c[2]), "+f"(c[3])
        : "r"(a[0]), "r"(a[1]), "r"(a[2]), "r"(a[3]), "r"(b0), "r"(b1));
}

__device__ __forceinline__ void cp16(void* smem_dst, const void* gmem_src, bool valid) {
    uint32_t d = (uint32_t)__cvta_generic_to_shared(smem_dst);
    int sz = valid ? 16 : 0;
    asm volatile("cp.async.cg.shared.global [%0], [%1], 16, %2;"
                 :: "r"(d), "l"(gmem_src), "r"(sz));
}

__device__ __forceinline__ uint32_t pack_h2(float a, float b) {
    __half2 h = __floats2half2_rn(a, b);
    return *(uint32_t*)&h;
}

// ---------------------------------------------------------------------------
// Kernel 0: vectorized CSR rowptr from sorted edge_dst (thread per 4 edges).
//   Runs on a parallel graph branch, concurrent with the GEMM.
// ---------------------------------------------------------------------------
__global__ void rowptr4_kernel(const int* __restrict__ edge_dst,
                               int* __restrict__ rowptr) {
    int i = blockIdx.x * blockDim.x + threadIdx.x;   // quad index
    if (i >= N_EDGES / 4) return;
    const int e0 = i * 4;
    int4 d = __ldg((const int4*)&edge_dst[e0]);
    const int lane = threadIdx.x & 31;
    int prev_n = __shfl_up_sync(0xffffffff, d.w, 1);
    int prev;
    if (lane == 0) {
        prev = (e0 == 0) ? -1 : __ldg(&edge_dst[e0 - 1]);
    } else {
        prev = prev_n;
    }
    int dd[4] = {d.x, d.y, d.z, d.w};
    #pragma unroll
    for (int j = 0; j < 4; j++) {
        for (int n = prev + 1; n <= dd[j]; n++) rowptr[n] = e0 + j;
        prev = dd[j];
    }
    if (e0 + 4 == N_EDGES) {
        for (int n = prev + 1; n <= N_NODES; n++) rowptr[n] = N_EDGES;
    }
}

// ---------------------------------------------------------------------------
// Kernel 1: support = x @ W^T + b  via fp16 m16n8k16 tensor cores.
//   In-register per-chunk W pack (double-buffered), cp.async x pipeline.
//   Block: 128 threads (4 warps), 128 rows. Warp: 32 rows x 64 cols.
//   smem: xs 24.6KB + whA/whB 4KB = 28.7KB. Output fp16.
// ---------------------------------------------------------------------------
#define KC 16
#define NCHUNK (D_IN / KC)   // 16
#define XSTR 24              // word stride: conflict-free float2 A-fragment reads
#define GEMM_BLOCKS ((N_NODES + 127) / 128)       // 391

__global__ __launch_bounds__(128) void gemm_f16_kernel(
    const float* __restrict__ x,
    const float* __restrict__ W,
    const float* __restrict__ bias,
    __half* __restrict__ support)
{
    __shared__ float    xs[2][128][XSTR];   // 24576 B
    __shared__ uint32_t whA[2][64][4];      // b0 halves (cols 0-7 of k16 slice)
    __shared__ uint32_t whB[2][64][4];      // b1 halves (cols 8-15)

    const int tid  = threadIdx.x;
    const int warp = tid >> 5;    // 0..3
    const int lane = tid & 31;
    const int gq   = lane >> 2;   // 0..7
    const int tq   = lane & 3;    // 0..3
    const int row_base = blockIdx.x * 128;

    const int xr  = tid >> 2;   // x staging base row
    const int xc4 = tid & 3;
    const int wn  = tid >> 1;   // W pack: n index
    const int wh  = tid & 1;    // 0 -> cols 0-7 (whA), 1 -> cols 8-15 (whB)

    // ---- fire x prefetch for chunk 0 ----
    {
        #pragma unroll
        for (int i = 0; i < 4; i++) {
            int r  = xr + i * 32;
            int gr = row_base + r;
            bool valid = gr < N_NODES;
            cp16(&xs[0][r][xc4 * 4], &x[(size_t)(valid ? gr : 0) * D_IN + xc4 * 4], valid);
        }
        asm volatile("cp.async.commit_group;" ::: "memory");
    }

    // ---- W chunk-0 slice: load + pack into buffer 0 ----
    const float4* wsrc0 = (const float4*)&W[wn * D_IN + wh * 8];
    float4 wa = __ldg(wsrc0 + 0);
    float4 wb = __ldg(wsrc0 + 1);
    {
        uint32_t* dst = wh ? &whB[0][wn][0] : &whA[0][wn][0];
        dst[0] = pack_h2(wa.x, wa.y);
        dst[1] = pack_h2(wa.z, wa.w);
        dst[2] = pack_h2(wb.x, wb.y);
        dst[3] = pack_h2(wb.z, wb.w);
    }

    float acc[2][8][4];
    #pragma unroll
    for (int t = 0; t < 2; t++)
        #pragma unroll
        for (int nt = 0; nt < 8; nt++)
            #pragma unroll
            for (int j = 0; j < 4; j++) acc[t][nt][j] = 0.f;

    int buf = 0;
    for (int c = 0; c < NCHUNK; c++) {
        if (c + 1 < NCHUNK) {
            const int kt = (c + 1) * KC;
            #pragma unroll
            for (int i = 0; i < 4; i++) {
                int r  = xr + i * 32;
                int gr = row_base + r;
                bool valid = gr < N_NODES;
                cp16(&xs[buf ^ 1][r][xc4 * 4], &x[(size_t)(valid ? gr : 0) * D_IN + kt + xc4 * 4], valid);
            }
            asm volatile("cp.async.commit_group;" ::: "memory");
            // next W slice loads land during this chunk's compute
            const float4* wsrc = (const float4*)&W[wn * D_IN + kt + wh * 8];
            wa = __ldg(wsrc + 0);
            wb = __ldg(wsrc + 1);
            asm volatile("cp.async.wait_group 1;" ::: "memory");
        } else {
            asm volatile("cp.async.wait_group 0;" ::: "memory");
        }
        __syncthreads();

        // ---- compute chunk c ----
        uint32_t a[2][4];
        #pragma unroll
        for (int t = 0; t < 2; t++) {
            const int r0 = warp * 32 + t * 16 + gq;
            float2 p0 = *(const float2*)&xs[buf][r0    ][2 * tq];
            float2 p1 = *(const float2*)&xs[buf][r0 + 8][2 * tq];
            float2 p2 = *(const float2*)&xs[buf][r0    ][2 * tq + 8];
            float2 p3 = *(const float2*)&xs[buf][r0 + 8][2 * tq + 8];
            a[t][0] = pack_h2(p0.x, p0.y);
            a[t][1] = pack_h2(p1.x, p1.y);
            a[t][2] = pack_h2(p2.x, p2.y);
            a[t][3] = pack_h2(p3.x, p3.y);
        }
        #pragma unroll
        for (int nt = 0; nt < 8; nt++) {
            const int n0 = nt * 8 + gq;
            uint32_t b0 = whA[buf][n0][tq];
            uint32_t b1 = whB[buf][n0][tq];
            mma_f16(acc[0][nt], a[0], b0, b1);
            mma_f16(acc[1][nt], a[1], b0, b1);
        }

        // ---- pack next W slice into buf^1 ----
        if (c + 1 < NCHUNK) {
            uint32_t* dst = wh ? &whB[buf ^ 1][wn][0] : &whA[buf ^ 1][wn][0];
            dst[0] = pack_h2(wa.x, wa.y);
            dst[1] = pack_h2(wa.z, wa.w);
            dst[2] = pack_h2(wb.x, wb.y);
            dst[3] = pack_h2(wb.z, wb.w);
        }
        __syncthreads();
        buf ^= 1;
    }

    // Epilogue: +bias, store as half2 (support row = 32 half2)
    __half2* sup2 = (__half2*)support;
    #pragma unroll
    for (int t = 0; t < 2; t++) {
        const int r_lo = row_base + warp * 32 + t * 16 + gq;
        const int r_hi = r_lo + 8;
        #pragma unroll
        for (int nt = 0; nt < 8; nt++) {
            int c0 = nt * 8 + tq * 2;
            float bx = bias[c0], by = bias[c0 + 1];
            int h2 = nt * 4 + tq;
            if (r_lo < N_NODES)
                sup2[(size_t)r_lo * 32 + h2] = __floats2half2_rn(acc[t][nt][0] + bx, acc[t][nt][1] + by);
            if (r_hi < N_NODES)
                sup2[(size_t)r_hi * 32 + h2] = __floats2half2_rn(acc[t][nt][2] + bx, acc[t][nt][3] + by);
        }
    }
}

// ---------------------------------------------------------------------------
// Kernel 2: aggregation + LeakyReLU (R10-exact best-measured form).
//   8 lanes per node, LDG.128 fp16 gather, pragma unroll 4.
// ---------------------------------------------------------------------------
__global__ __launch_bounds__(256) void agg_node_kernel(
    const int*   __restrict__ edge_src,
    const float* __restrict__ edge_val,
    const int*   __restrict__ rowptr,
    const uint4* __restrict__ support8,   // fp16 rows: 8 uint4 each
    float4*      __restrict__ out4)
{
    const int warpid = (blockIdx.x * blockDim.x + threadIdx.x) >> 5;
    const int lane   = threadIdx.x & 31;
    const int node   = warpid * 4 + (lane >> 3);
    const int c8     = lane & 7;          // uint4 (8-column) slot
    if (node >= N_NODES) return;

    const int beg = __ldg(&rowptr[node]);
    const int end = __ldg(&rowptr[node + 1]);

    float acc[8];
    #pragma unroll
    for (int j = 0; j < 8; j++) acc[j] = 0.f;

    #pragma unroll 4
    for (int e = beg; e < end; e++) {
        const int   s = __ldg(&edge_src[e]);     // uniform within octet
        const float v = __ldg(&edge_val[e]);
        uint4 raw = __ldg(&support8[(size_t)s * 8 + c8]);
        float2 f0 = __half22float2(*(__half2*)&raw.x);
        float2 f1 = __half22float2(*(__half2*)&raw.y);
        float2 f2 = __half22float2(*(__half2*)&raw.z);
        float2 f3 = __half22float2(*(__half2*)&raw.w);
        acc[0] += v * f0.x;  acc[1] += v * f0.y;
        acc[2] += v * f1.x;  acc[3] += v * f1.y;
        acc[4] += v * f2.x;  acc[5] += v * f2.y;
        acc[6] += v * f3.x;  acc[7] += v * f3.y;
    }
    #pragma unroll
    for (int j = 0; j < 8; j++)
        acc[j] = (acc[j] >= 0.f) ? acc[j] : NEG_SLOPE * acc[j];

    const size_t ob = (size_t)node * 16 + c8 * 2;
    out4[ob]     = make_float4(acc[0], acc[1], acc[2], acc[3]);
    out4[ob + 1] = make_float4(acc[4], acc[5], acc[6], acc[7]);
}

// ---------------------------------------------------------------------------
// Launch: rowptr runs on a parallel graph branch, concurrent with the GEMM.
//   fork:  event on capture(legacy) stream -> side stream waits
//   join:  event on side stream -> legacy stream waits before agg
// ---------------------------------------------------------------------------
extern "C" void kernel_launch(void* const* d_in, const int* in_sizes, int n_in,
                              void* d_out, int out_size) {
    const float* x        = (const float*)d_in[0];
    const float* W        = (const float*)d_in[1];
    const float* b        = (const float*)d_in[2];
    const int*   edge_src = (const int*)  d_in[3];
    const int*   edge_dst = (const int*)  d_in[4];
    const float* edge_val = (const float*)d_in[5];
    float* out = (float*)d_out;

    __half* support;
    cudaGetSymbolAddress((void**)&support, g_support);
    int* rowptr;
    cudaGetSymbolAddress((void**)&rowptr, g_rowptr);

    cudaStream_t side;
    cudaStreamCreateWithFlags(&side, cudaStreamNonBlocking);
    cudaEvent_t ev_fork, ev_join;
    cudaEventCreateWithFlags(&ev_fork, cudaEventDisableTiming);
    cudaEventCreateWithFlags(&ev_join, cudaEventDisableTiming);

    // fork side branch off the (capturing) legacy stream
    cudaEventRecord(ev_fork, 0);
    cudaStreamWaitEvent(side, ev_fork, 0);

    // branch A (side): rowptr
    rowptr4_kernel<<<(N_EDGES / 4 + 255) / 256, 256, 0, side>>>(edge_dst, rowptr);
    cudaEventRecord(ev_join, side);

    // branch B (main): fp16 tensor-core projection (self-packs W)
    gemm_f16_kernel<<<GEMM_BLOCKS, 128>>>(x, W, b, support);

    // join, then aggregation
    cudaStreamWaitEvent(0, ev_join, 0);
    const int n_warps  = (N_NODES + 3) / 4;            // 12500
    const int n_blocks = (n_warps * 32 + 255) / 256;   // 1563
    agg_node_kernel<<<n_blocks, 256>>>(edge_src, edge_val, rowptr,
                                       (const uint4*)support, (float4*)out);
}

// round 16
// speedup vs baseline: 1.0915x; 1.0915x over previous
#include <cuda_runtime.h>
#include <cuda_fp16.h>
#include <cstdint>

#define N_NODES 50000
#define N_EDGES 800000
#define D_IN    256
#define D_OUT   64
#define NEG_SLOPE 0.2f

// Scratch: support = x @ W^T + b  stored as fp16  [N_NODES, D_OUT]
__device__ __half g_support[N_NODES * D_OUT];
// CSR row pointers for sorted edge_dst
__device__ int g_rowptr[N_NODES + 1];
// W as fp16 B-fragment pairs: [n][kb16][tq] -> uint2{ h2(W[n][16kb+2tq],W[..+1]),
//                                                     h2(W[n][16kb+2tq+8],W[..+9]) }
__device__ uint2 g_whp[D_OUT * (D_IN / 16) * 4];   // 4096 uint2

// ---------------------------------------------------------------------------
// fp16 m16n8k16 mma
// ---------------------------------------------------------------------------
__device__ __forceinline__ void mma_f16(float c[4], const uint32_t a[4], uint32_t b0, uint32_t b1) {
    asm volatile(
        "mma.sync.aligned.m16n8k16.row.col.f32.f16.f16.f32 "
        "{%0,%1,%2,%3}, {%4,%5,%6,%7}, {%8,%9}, {%0,%1,%2,%3};"
        : "+f"(c[0]), "+f"(c[1]), "+f"(c[2]), "+f"(c[3])
        : "r"(a[0]), "r"(a[1]), "r"(a[2]), "r"(a[3]), "r"(b0), "r"(b1));
}

__device__ __forceinline__ void cp16(void* smem_dst, const void* gmem_src, bool valid) {
    uint32_t d = (uint32_t)__cvta_generic_to_shared(smem_dst);
    int sz = valid ? 16 : 0;
    asm volatile("cp.async.cg.shared.global [%0], [%1], 16, %2;"
                 :: "r"(d), "l"(gmem_src), "r"(sz));
}

__device__ __forceinline__ uint32_t pack_h2(float a, float b) {
    __half2 h = __floats2half2_rn(a, b);
    return *(uint32_t*)&h;
}

// ---------------------------------------------------------------------------
// Kernel 0: fused prep — W fp16 pack (first 4096 threads) + rowptr.
//   One thread per 16 edges: 4 independent int4 loads (MLP=4) + 1 scalar prev.
// ---------------------------------------------------------------------------
#define FILL4(da, db, dc, dd_, ebase)                                  \
    do {                                                               \
        for (int n = prev + 1; n <= (da); n++) rowptr[n] = (ebase);    \
        prev = (da);                                                   \
        for (int n = prev + 1; n <= (db); n++) rowptr[n] = (ebase)+1;  \
        prev = (db);                                                   \
        for (int n = prev + 1; n <= (dc); n++) rowptr[n] = (ebase)+2;  \
        prev = (dc);                                                   \
        for (int n = prev + 1; n <= (dd_); n++) rowptr[n] = (ebase)+3; \
        prev = (dd_);                                                  \
    } while (0)

__global__ void prep_kernel(const int* __restrict__ edge_dst,
                            int* __restrict__ rowptr,
                            const float* __restrict__ W,
                            uint2* __restrict__ whp) {
    int i = blockIdx.x * blockDim.x + threadIdx.x;

    if (i < D_OUT * (D_IN / 16) * 4) {   // 4096
        int n  = i >> 6;
        int kb = (i >> 2) & 15;
        int tq = i & 3;
        const float* wr = &W[n * D_IN + kb * 16];
        uint2 v;
        v.x = pack_h2(__ldg(&wr[2 * tq]),     __ldg(&wr[2 * tq + 1]));
        v.y = pack_h2(__ldg(&wr[2 * tq + 8]), __ldg(&wr[2 * tq + 9]));
        whp[i] = v;
    }

    if (i < N_EDGES / 16) {              // 50000
        const int e0 = i * 16;
        // 4 independent vector loads (MLP) + 1 scalar prev per 16 edges
        int4 d0 = __ldg((const int4*)&edge_dst[e0]);
        int4 d1 = __ldg((const int4*)&edge_dst[e0 + 4]);
        int4 d2 = __ldg((const int4*)&edge_dst[e0 + 8]);
        int4 d3 = __ldg((const int4*)&edge_dst[e0 + 12]);
        int prev = (e0 == 0) ? -1 : __ldg(&edge_dst[e0 - 1]);

        FILL4(d0.x, d0.y, d0.z, d0.w, e0);
        FILL4(d1.x, d1.y, d1.z, d1.w, e0 + 4);
        FILL4(d2.x, d2.y, d2.z, d2.w, e0 + 8);
        FILL4(d3.x, d3.y, d3.z, d3.w, e0 + 12);

        if (e0 + 16 == N_EDGES) {
            for (int n = prev + 1; n <= N_NODES; n++) rowptr[n] = N_EDGES;
        }
    }
}

// ---------------------------------------------------------------------------
// Kernel 1: support = x @ W^T + b  via fp16 m16n8k16 tensor cores.
//   (R10-exact.) Block: 128 threads (4 warps), 128 rows. Warp: 32x64.
//   cp.async double-buffered, K chunks of 16. Output fp16.
// ---------------------------------------------------------------------------
#define KC 16
#define NCHUNK (D_IN / KC)   // 16
#define XSTR 24              // word stride: conflict-free float2 A-fragment reads

__global__ __launch_bounds__(128) void gemm_f16_kernel(
    const float* __restrict__ x,
    const uint2* __restrict__ whp,
    const float* __restrict__ bias,
    __half* __restrict__ support)
{
    __shared__ float xs[2][128][XSTR];
    __shared__ uint2 wh_s[2][64][4];   // stride 4 uint2: conflict-free (gq*4+tq mod 16)

    const int tid  = threadIdx.x;
    const int warp = tid >> 5;    // 0..3
    const int lane = tid & 31;
    const int gq   = lane >> 2;   // 0..7
    const int tq   = lane & 3;    // 0..3
    const int row_base = blockIdx.x * 128;

    float acc[2][8][4];
    #pragma unroll
    for (int t = 0; t < 2; t++)
        #pragma unroll
        for (int nt = 0; nt < 8; nt++)
            #pragma unroll
            for (int j = 0; j < 4; j++) acc[t][nt][j] = 0.f;

    const int xr  = tid >> 2;   // x staging base row
    const int xc4 = tid & 3;
    const int wn  = tid >> 1;   // W staging n (0..63)
    const int wq  = tid & 1;

    // prologue: stage chunk 0 -> buf 0
    {
        #pragma unroll
        for (int i = 0; i < 4; i++) {
            int r  = xr + i * 32;
            int gr = row_base + r;
            bool valid = gr < N_NODES;
            cp16(&xs[0][r][xc4 * 4], &x[(size_t)(valid ? gr : 0) * D_IN + xc4 * 4], valid);
        }
        cp16(&wh_s[0][wn][wq * 2], &((const uint4*)whp)[wn * 32 + wq], true);
        asm volatile("cp.async.commit_group;" ::: "memory");
    }

    int buf = 0;
    for (int c = 0; c < NCHUNK; c++) {
        if (c + 1 < NCHUNK) {
            const int kt = (c + 1) * KC;
            #pragma unroll
            for (int i = 0; i < 4; i++) {
                int r  = xr + i * 32;
                int gr = row_base + r;
                bool valid = gr < N_NODES;
                cp16(&xs[buf ^ 1][r][xc4 * 4], &x[(size_t)(valid ? gr : 0) * D_IN + kt + xc4 * 4], valid);
            }
            cp16(&wh_s[buf ^ 1][wn][wq * 2], &((const uint4*)whp)[wn * 32 + (c + 1) * 2 + wq], true);
            asm volatile("cp.async.commit_group;" ::: "memory");
            asm volatile("cp.async.wait_group 1;" ::: "memory");
        } else {
            asm volatile("cp.async.wait_group 0;" ::: "memory");
        }
        __syncthreads();

        uint32_t a[2][4];
        #pragma unroll
        for (int t = 0; t < 2; t++) {
            const int r0 = warp * 32 + t * 16 + gq;
            float2 p0 = *(const float2*)&xs[buf][r0    ][2 * tq];
            float2 p1 = *(const float2*)&xs[buf][r0 + 8][2 * tq];
            float2 p2 = *(const float2*)&xs[buf][r0    ][2 * tq + 8];
            float2 p3 = *(const float2*)&xs[buf][r0 + 8][2 * tq + 8];
            a[t][0] = pack_h2(p0.x, p0.y);
            a[t][1] = pack_h2(p1.x, p1.y);
            a[t][2] = pack_h2(p2.x, p2.y);
            a[t][3] = pack_h2(p3.x, p3.y);
        }
        #pragma unroll
        for (int nt = 0; nt < 8; nt++) {
            uint2 bb = wh_s[buf][nt * 8 + gq][tq];
            mma_f16(acc[0][nt], a[0], bb.x, bb.y);
            mma_f16(acc[1][nt], a[1], bb.x, bb.y);
        }
        __syncthreads();
        buf ^= 1;
    }

    // Epilogue: +bias, store as half2 (support row = 32 half2)
    __half2* sup2 = (__half2*)support;
    #pragma unroll
    for (int t = 0; t < 2; t++) {
        const int r_lo = row_base + warp * 32 + t * 16 + gq;
        const int r_hi = r_lo + 8;
        #pragma unroll
        for (int nt = 0; nt < 8; nt++) {
            int c0 = nt * 8 + tq * 2;
            float bx = bias[c0], by = bias[c0 + 1];
            int h2 = nt * 4 + tq;
            if (r_lo < N_NODES)
                sup2[(size_t)r_lo * 32 + h2] = __floats2half2_rn(acc[t][nt][0] + bx, acc[t][nt][1] + by);
            if (r_hi < N_NODES)
                sup2[(size_t)r_hi * 32 + h2] = __floats2half2_rn(acc[t][nt][2] + bx, acc[t][nt][3] + by);
        }
    }
}

// ---------------------------------------------------------------------------
// Kernel 2: aggregation + LeakyReLU (R10-exact best-measured form).
//   8 lanes per node, LDG.128 fp16 gather, pragma unroll 4.
// ---------------------------------------------------------------------------
__global__ __launch_bounds__(256) void agg_node_kernel(
    const int*   __restrict__ edge_src,
    const float* __restrict__ edge_val,
    const int*   __restrict__ rowptr,
    const uint4* __restrict__ support8,   // fp16 rows: 8 uint4 each
    float4*      __restrict__ out4)
{
    const int warpid = (blockIdx.x * blockDim.x + threadIdx.x) >> 5;
    const int lane   = threadIdx.x & 31;
    const int node   = warpid * 4 + (lane >> 3);
    const int c8     = lane & 7;          // uint4 (8-column) slot
    if (node >= N_NODES) return;

    const int beg = __ldg(&rowptr[node]);
    const int end = __ldg(&rowptr[node + 1]);

    float acc[8];
    #pragma unroll
    for (int j = 0; j < 8; j++) acc[j] = 0.f;

    #pragma unroll 4
    for (int e = beg; e < end; e++) {
        const int   s = __ldg(&edge_src[e]);     // uniform within octet
        const float v = __ldg(&edge_val[e]);
        uint4 raw = __ldg(&support8[(size_t)s * 8 + c8]);
        float2 f0 = __half22float2(*(__half2*)&raw.x);
        float2 f1 = __half22float2(*(__half2*)&raw.y);
        float2 f2 = __half22float2(*(__half2*)&raw.z);
        float2 f3 = __half22float2(*(__half2*)&raw.w);
        acc[0] += v * f0.x;  acc[1] += v * f0.y;
        acc[2] += v * f1.x;  acc[3] += v * f1.y;
        acc[4] += v * f2.x;  acc[5] += v * f2.y;
        acc[6] += v * f3.x;  acc[7] += v * f3.y;
    }
    #pragma unroll
    for (int j = 0; j < 8; j++)
        acc[j] = (acc[j] >= 0.f) ? acc[j] : NEG_SLOPE * acc[j];

    const size_t ob = (size_t)node * 16 + c8 * 2;
    out4[ob]     = make_float4(acc[0], acc[1], acc[2], acc[3]);
    out4[ob + 1] = make_float4(acc[4], acc[5], acc[6], acc[7]);
}

// ---------------------------------------------------------------------------
// Launch (R10 structure: 3 serial kernels)
// ---------------------------------------------------------------------------
extern "C" void kernel_launch(void* const* d_in, const int* in_sizes, int n_in,
                              void* d_out, int out_size) {
    const float* x        = (const float*)d_in[0];
    const float* W        = (const float*)d_in[1];
    const float* b        = (const float*)d_in[2];
    const int*   edge_src = (const int*)  d_in[3];
    const int*   edge_dst = (const int*)  d_in[4];
    const float* edge_val = (const float*)d_in[5];
    float* out = (float*)d_out;

    __half* support;
    cudaGetSymbolAddress((void**)&support, g_support);
    int* rowptr;
    cudaGetSymbolAddress((void**)&rowptr, g_rowptr);
    uint2* whp;
    cudaGetSymbolAddress((void**)&whp, g_whp);

    // 0. fused prep: W fp16 pack + rowptr (thread per 16 edges, MLP=4)
    prep_kernel<<<(N_EDGES / 16 + 255) / 256, 256>>>(edge_dst, rowptr, W, whp);

    // 1. fp16 tensor-core projection -> fp16 support
    gemm_f16_kernel<<<(N_NODES + 127) / 128, 128>>>(x, whp, b, support);

    // 2. fused aggregation + LeakyReLU (8 lanes per node)
    const int n_warps  = (N_NODES + 3) / 4;            // 12500
    const int n_blocks = (n_warps * 32 + 255) / 256;   // 1563
    agg_node_kernel<<<n_blocks, 256>>>(edge_src, edge_val, rowptr,
                                       (const uint4*)support, (float4*)out);
}

// round 17
// speedup vs baseline: 1.1460x; 1.0499x over previous
#include <cuda_runtime.h>
#include <cuda_fp16.h>
#include <cstdint>

#define N_NODES 50000
#define N_EDGES 800000
#define D_IN    256
#define D_OUT   64
#define NEG_SLOPE 0.2f

// Scratch: support = x @ W^T + b  stored as fp16  [N_NODES, D_OUT]
__device__ __half g_support[N_NODES * D_OUT];
// CSR row pointers for sorted edge_dst
__device__ int g_rowptr[N_NODES + 1];
// W as fp16 B-fragment pairs: [n][kb16][tq] -> uint2{ h2(W[n][16kb+2tq],W[..+1]),
//                                                     h2(W[n][16kb+2tq+8],W[..+9]) }
__device__ uint2 g_whp[D_OUT * (D_IN / 16) * 4];   // 4096 uint2

// ---------------------------------------------------------------------------
// fp16 m16n8k16 mma
// ---------------------------------------------------------------------------
__device__ __forceinline__ void mma_f16(float c[4], const uint32_t a[4], uint32_t b0, uint32_t b1) {
    asm volatile(
        "mma.sync.aligned.m16n8k16.row.col.f32.f16.f16.f32 "
        "{%0,%1,%2,%3}, {%4,%5,%6,%7}, {%8,%9}, {%0,%1,%2,%3};"
        : "+f"(c[0]), "+f"(c[1]), "+f"(c[2]), "+f"(c[3])
        : "r"(a[0]), "r"(a[1]), "r"(a[2]), "r"(a[3]), "r"(b0), "r"(b1));
}

__device__ __forceinline__ void cp16(void* smem_dst, const void* gmem_src, bool valid) {
    uint32_t d = (uint32_t)__cvta_generic_to_shared(smem_dst);
    int sz = valid ? 16 : 0;
    asm volatile("cp.async.cg.shared.global [%0], [%1], 16, %2;"
                 :: "r"(d), "l"(gmem_src), "r"(sz));
}

__device__ __forceinline__ uint32_t pack_h2(float a, float b) {
    __half2 h = __floats2half2_rn(a, b);
    return *(uint32_t*)&h;
}

// ---------------------------------------------------------------------------
// Kernel 0: fused prep — W fp16 pack (first 4096 threads) + rowptr quads.
//   (R10-exact: one thread per 4 edges, shfl-based prev.)
// ---------------------------------------------------------------------------
__global__ void prep_kernel(const int* __restrict__ edge_dst,
                            int* __restrict__ rowptr,
                            const float* __restrict__ W,
                            uint2* __restrict__ whp) {
    int i = blockIdx.x * blockDim.x + threadIdx.x;

    if (i < D_OUT * (D_IN / 16) * 4) {   // 4096
        int n  = i >> 6;
        int kb = (i >> 2) & 15;
        int tq = i & 3;
        const float* wr = &W[n * D_IN + kb * 16];
        uint2 v;
        v.x = pack_h2(__ldg(&wr[2 * tq]),     __ldg(&wr[2 * tq + 1]));
        v.y = pack_h2(__ldg(&wr[2 * tq + 8]), __ldg(&wr[2 * tq + 9]));
        whp[i] = v;
    }

    if (i < N_EDGES / 4) {
        const int e0 = i * 4;
        int4 d = __ldg((const int4*)&edge_dst[e0]);
        const int lane = threadIdx.x & 31;
        int prev_n = __shfl_up_sync(0xffffffff, d.w, 1);
        int prev;
        if (lane == 0) {
            prev = (e0 == 0) ? -1 : __ldg(&edge_dst[e0 - 1]);
        } else {
            prev = prev_n;
        }
        int dd[4] = {d.x, d.y, d.z, d.w};
        #pragma unroll
        for (int j = 0; j < 4; j++) {
            for (int n = prev + 1; n <= dd[j]; n++) rowptr[n] = e0 + j;
            prev = dd[j];
        }
        if (e0 + 4 == N_EDGES) {
            for (int n = prev + 1; n <= N_NODES; n++) rowptr[n] = N_EDGES;
        }
    }
}

// ---------------------------------------------------------------------------
// Kernel 1: support = x @ W^T + b  via fp16 m16n8k16 tensor cores.
//   (R10-exact.) Block: 128 threads (4 warps), 128 rows. Warp: 32x64.
//   cp.async double-buffered, K chunks of 16. Output fp16.
// ---------------------------------------------------------------------------
#define KC 16
#define NCHUNK (D_IN / KC)   // 16
#define XSTR 24              // word stride: conflict-free float2 A-fragment reads

__global__ __launch_bounds__(128) void gemm_f16_kernel(
    const float* __restrict__ x,
    const uint2* __restrict__ whp,
    const float* __restrict__ bias,
    __half* __restrict__ support)
{
    __shared__ float xs[2][128][XSTR];
    __shared__ uint2 wh_s[2][64][4];   // stride 4 uint2: conflict-free (gq*4+tq mod 16)

    const int tid  = threadIdx.x;
    const int warp = tid >> 5;    // 0..3
    const int lane = tid & 31;
    const int gq   = lane >> 2;   // 0..7
    const int tq   = lane & 3;    // 0..3
    const int row_base = blockIdx.x * 128;

    float acc[2][8][4];
    #pragma unroll
    for (int t = 0; t < 2; t++)
        #pragma unroll
        for (int nt = 0; nt < 8; nt++)
            #pragma unroll
            for (int j = 0; j < 4; j++) acc[t][nt][j] = 0.f;

    const int xr  = tid >> 2;   // x staging base row
    const int xc4 = tid & 3;
    const int wn  = tid >> 1;   // W staging n (0..63)
    const int wq  = tid & 1;

    // prologue: stage chunk 0 -> buf 0
    {
        #pragma unroll
        for (int i = 0; i < 4; i++) {
            int r  = xr + i * 32;
            int gr = row_base + r;
            bool valid = gr < N_NODES;
            cp16(&xs[0][r][xc4 * 4], &x[(size_t)(valid ? gr : 0) * D_IN + xc4 * 4], valid);
        }
        cp16(&wh_s[0][wn][wq * 2], &((const uint4*)whp)[wn * 32 + wq], true);
        asm volatile("cp.async.commit_group;" ::: "memory");
    }

    int buf = 0;
    for (int c = 0; c < NCHUNK; c++) {
        if (c + 1 < NCHUNK) {
            const int kt = (c + 1) * KC;
            #pragma unroll
            for (int i = 0; i < 4; i++) {
                int r  = xr + i * 32;
                int gr = row_base + r;
                bool valid = gr < N_NODES;
                cp16(&xs[buf ^ 1][r][xc4 * 4], &x[(size_t)(valid ? gr : 0) * D_IN + kt + xc4 * 4], valid);
            }
            cp16(&wh_s[buf ^ 1][wn][wq * 2], &((const uint4*)whp)[wn * 32 + (c + 1) * 2 + wq], true);
            asm volatile("cp.async.commit_group;" ::: "memory");
            asm volatile("cp.async.wait_group 1;" ::: "memory");
        } else {
            asm volatile("cp.async.wait_group 0;" ::: "memory");
        }
        __syncthreads();

        uint32_t a[2][4];
        #pragma unroll
        for (int t = 0; t < 2; t++) {
            const int r0 = warp * 32 + t * 16 + gq;
            float2 p0 = *(const float2*)&xs[buf][r0    ][2 * tq];
            float2 p1 = *(const float2*)&xs[buf][r0 + 8][2 * tq];
            float2 p2 = *(const float2*)&xs[buf][r0    ][2 * tq + 8];
            float2 p3 = *(const float2*)&xs[buf][r0 + 8][2 * tq + 8];
            a[t][0] = pack_h2(p0.x, p0.y);
            a[t][1] = pack_h2(p1.x, p1.y);
            a[t][2] = pack_h2(p2.x, p2.y);
            a[t][3] = pack_h2(p3.x, p3.y);
        }
        #pragma unroll
        for (int nt = 0; nt < 8; nt++) {
            uint2 bb = wh_s[buf][nt * 8 + gq][tq];
            mma_f16(acc[0][nt], a[0], bb.x, bb.y);
            mma_f16(acc[1][nt], a[1], bb.x, bb.y);
        }
        __syncthreads();
        buf ^= 1;
    }

    // Epilogue: +bias, store as half2 (support row = 32 half2)
    __half2* sup2 = (__half2*)support;
    #pragma unroll
    for (int t = 0; t < 2; t++) {
        const int r_lo = row_base + warp * 32 + t * 16 + gq;
        const int r_hi = r_lo + 8;
        #pragma unroll
        for (int nt = 0; nt < 8; nt++) {
            int c0 = nt * 8 + tq * 2;
            float bx = bias[c0], by = bias[c0 + 1];
            int h2 = nt * 4 + tq;
            if (r_lo < N_NODES)
                sup2[(size_t)r_lo * 32 + h2] = __floats2half2_rn(acc[t][nt][0] + bx, acc[t][nt][1] + by);
            if (r_hi < N_NODES)
                sup2[(size_t)r_hi * 32 + h2] = __floats2half2_rn(acc[t][nt][2] + bx, acc[t][nt][3] + by);
        }
    }
}

// ---------------------------------------------------------------------------
// Kernel 2: aggregation + LeakyReLU. 8 lanes per node, LDG.128 fp16 gather.
//   Persistent single-wave grid (888 blocks = 48 warps/SM): each octet
//   grid-strides over nodes. Inner loop body is R10-exact.
// ---------------------------------------------------------------------------
#define AGG_BLOCKS 888
#define AGG_OCTETS (AGG_BLOCKS * 32)   // 28416 octets (256 thr = 32 octets/block)

__global__ __launch_bounds__(256) void agg_node_kernel(
    const int*   __restrict__ edge_src,
    const float* __restrict__ edge_val,
    const int*   __restrict__ rowptr,
    const uint4* __restrict__ support8,   // fp16 rows: 8 uint4 each
    float4*      __restrict__ out4)
{
    const int octet = (blockIdx.x * blockDim.x + threadIdx.x) >> 3;
    const int c8    = threadIdx.x & 7;    // uint4 (8-column) slot

    for (int node = octet; node < N_NODES; node += AGG_OCTETS) {
        const int beg = __ldg(&rowptr[node]);
        const int end = __ldg(&rowptr[node + 1]);

        float acc[8];
        #pragma unroll
        for (int j = 0; j < 8; j++) acc[j] = 0.f;

        #pragma unroll 4
        for (int e = beg; e < end; e++) {
            const int   s = __ldg(&edge_src[e]);     // uniform within octet
            const float v = __ldg(&edge_val[e]);
            uint4 raw = __ldg(&support8[(size_t)s * 8 + c8]);
            float2 f0 = __half22float2(*(__half2*)&raw.x);
            float2 f1 = __half22float2(*(__half2*)&raw.y);
            float2 f2 = __half22float2(*(__half2*)&raw.z);
            float2 f3 = __half22float2(*(__half2*)&raw.w);
            acc[0] += v * f0.x;  acc[1] += v * f0.y;
            acc[2] += v * f1.x;  acc[3] += v * f1.y;
            acc[4] += v * f2.x;  acc[5] += v * f2.y;
            acc[6] += v * f3.x;  acc[7] += v * f3.y;
        }
        #pragma unroll
        for (int j = 0; j < 8; j++)
            acc[j] = (acc[j] >= 0.f) ? acc[j] : NEG_SLOPE * acc[j];

        const size_t ob = (size_t)node * 16 + c8 * 2;
        out4[ob]     = make_float4(acc[0], acc[1], acc[2], acc[3]);
        out4[ob + 1] = make_float4(acc[4], acc[5], acc[6], acc[7]);
    }
}

// ---------------------------------------------------------------------------
// Launch (R10 structure: 3 serial kernels)
// ---------------------------------------------------------------------------
extern "C" void kernel_launch(void* const* d_in, const int* in_sizes, int n_in,
                              void* d_out, int out_size) {
    const float* x        = (const float*)d_in[0];
    const float* W        = (const float*)d_in[1];
    const float* b        = (const float*)d_in[2];
    const int*   edge_src = (const int*)  d_in[3];
    const int*   edge_dst = (const int*)  d_in[4];
    const float* edge_val = (const float*)d_in[5];
    float* out = (float*)d_out;

    __half* support;
    cudaGetSymbolAddress((void**)&support, g_support);
    int* rowptr;
    cudaGetSymbolAddress((void**)&rowptr, g_rowptr);
    uint2* whp;
    cudaGetSymbolAddress((void**)&whp, g_whp);

    // 0. fused prep: W fp16 pack + rowptr (R10-exact quad version)
    prep_kernel<<<(N_EDGES / 4 + 255) / 256, 256>>>(edge_dst, rowptr, W, whp);

    // 1. fp16 tensor-core projection -> fp16 support
    gemm_f16_kernel<<<(N_NODES + 127) / 128, 128>>>(x, whp, b, support);

    // 2. fused aggregation + LeakyReLU (single-wave persistent octets)
    agg_node_kernel<<<AGG_BLOCKS, 256>>>(edge_src, edge_val, rowptr,
                                         (const uint4*)support, (float4*)out);
}